// round 1
// baseline (speedup 1.0000x reference)
#include <cuda_runtime.h>

// ---------------------------------------------------------------------------
// MegNet layer, fused. FP32 with packed f32x2 FMA accumulation.
//   phi_e: [a1|a2|bond|state](128) -> 64 -> 64 -> 32 (SELU), per bond (2M)
//          + scatter-add into per-atom accumulator + bond-feature colsum
//   phi_v: [b2a/cnt|atom|state](96) -> 64 -> 64 -> 32, per atom (100K)
//          + atom-feature colsum
//   phi_u: [mean(bonds_new)|mean(atoms_new)|state](96) -> ... -> 32
// Output layout: [bonds_new (2M*32) | atoms_new (100K*32) | state_new (32)]
// ---------------------------------------------------------------------------

#define MAX_ATOMS 100000

__device__ __align__(16) float g_b2a[MAX_ATOMS * 32];
__device__ float g_cnt[MAX_ATOMS];
__device__ float g_bsum[32];
__device__ float g_asum[32];

typedef unsigned long long ull;

__device__ __forceinline__ ull pack2(float x) {
    ull r; asm("mov.b64 %0, {%1, %1};" : "=l"(r) : "f"(x)); return r;
}
__device__ __forceinline__ void fma2(ull& a, ull w, ull x) {
    asm("fma.rn.f32x2 %0, %1, %2, %0;" : "+l"(a) : "l"(w), "l"(x));
}
__device__ __forceinline__ void unpack2(ull v, float& lo, float& hi) {
    asm("mov.b64 {%0, %1}, %2;" : "=f"(lo), "=f"(hi) : "l"(v));
}

__device__ __forceinline__ float selu(float x) {
    return 1.0507009873554805f * (x > 0.f ? x : 1.6732632423543772f * expm1f(x));
}

// Accumulate 4 consecutive input features (one float4) against a 64-wide
// layer. acc[32] holds 64 fp32 outputs as packed pairs. wrow0 points at the
// shared-memory weight row for the first of the 4 features (row stride 64).
__device__ __forceinline__ void acc64_f4(ull acc[32], float4 xv, const float* wrow0) {
    float xs[4] = {xv.x, xv.y, xv.z, xv.w};
#pragma unroll
    for (int q = 0; q < 4; q++) {
        ull xp = pack2(xs[q]);
        const ulonglong2* wr = reinterpret_cast<const ulonglong2*>(wrow0 + q * 64);
#pragma unroll
        for (int jj = 0; jj < 16; jj++) {
            ulonglong2 w = wr[jj];
            fma2(acc[2 * jj + 0], w.x, xp);
            fma2(acc[2 * jj + 1], w.y, xp);
        }
    }
}

// ---------------------------------------------------------------------------
// Zero scratch (must run every graph replay)
// ---------------------------------------------------------------------------
__global__ void zero_kernel(int n_atoms) {
    int idx = blockIdx.x * blockDim.x + threadIdx.x;
    int stride = gridDim.x * blockDim.x;
    int nb = n_atoms * 32;
    for (int i = idx; i < nb; i += stride) g_b2a[i] = 0.f;
    for (int i = idx; i < n_atoms; i += stride) g_cnt[i] = 0.f;
    if (idx < 32) { g_bsum[idx] = 0.f; g_asum[idx] = 0.f; }
}

// ---------------------------------------------------------------------------
// phi_e: one thread per bond
// smem: w1(8192) w2(4096) w3(2048) b1(64) b2(64) b3(32) state(32) red(256)
// ---------------------------------------------------------------------------
__global__ void __launch_bounds__(256)
phi_e_kernel(const float* __restrict__ bonds,
             const int* __restrict__ ba1, const int* __restrict__ ba2,
             const float* __restrict__ atoms, const float* __restrict__ state,
             const float* __restrict__ w1, const float* __restrict__ b1,
             const float* __restrict__ w2, const float* __restrict__ b2,
             const float* __restrict__ w3, const float* __restrict__ b3,
             float* __restrict__ out_bonds, int n_bonds) {
    extern __shared__ float smem[];
    float* s_w1 = smem;             // 8192
    float* s_w2 = s_w1 + 8192;      // 4096
    float* s_w3 = s_w2 + 4096;      // 2048
    float* s_b1 = s_w3 + 2048;      // 64
    float* s_b2 = s_b1 + 64;        // 64
    float* s_b3 = s_b2 + 64;        // 32
    float* s_st = s_b3 + 32;        // 32
    float* s_red = s_st + 32;       // 8 warps * 32

    int tid = threadIdx.x;
    for (int i = tid; i < 8192; i += 256) s_w1[i] = w1[i];
    for (int i = tid; i < 4096; i += 256) s_w2[i] = w2[i];
    for (int i = tid; i < 2048; i += 256) s_w3[i] = w3[i];
    if (tid < 64) { s_b1[tid] = b1[tid]; s_b2[tid] = b2[tid]; }
    if (tid < 32) { s_b3[tid] = b3[tid]; s_st[tid] = state[tid]; }
    __syncthreads();

    int e = blockIdx.x * 256 + tid;
    bool active = e < n_bonds;
    float y[32];
    int i1 = 0;

    if (active) {
        i1 = ba1[e];
        int i2 = ba2[e];

        // ----- layer 1: 128 -> 64 -----
        ull acc[32];
        const ull* b1p = reinterpret_cast<const ull*>(s_b1);
#pragma unroll
        for (int jj = 0; jj < 32; jj++) acc[jj] = b1p[jj];

        const float4* a1v = reinterpret_cast<const float4*>(atoms + (size_t)i1 * 32);
        const float4* a2v = reinterpret_cast<const float4*>(atoms + (size_t)i2 * 32);
        const float4* bv  = reinterpret_cast<const float4*>(bonds + (size_t)e * 32);
        const float4* sv  = reinterpret_cast<const float4*>(s_st);
#pragma unroll
        for (int kk = 0; kk < 8; kk++) acc64_f4(acc, a1v[kk], s_w1 + (kk * 4) * 64);
#pragma unroll
        for (int kk = 0; kk < 8; kk++) acc64_f4(acc, a2v[kk], s_w1 + (32 + kk * 4) * 64);
#pragma unroll
        for (int kk = 0; kk < 8; kk++) acc64_f4(acc, bv[kk], s_w1 + (64 + kk * 4) * 64);
#pragma unroll
        for (int kk = 0; kk < 8; kk++) acc64_f4(acc, sv[kk], s_w1 + (96 + kk * 4) * 64);

        float h[64];
#pragma unroll
        for (int jj = 0; jj < 32; jj++) unpack2(acc[jj], h[2 * jj], h[2 * jj + 1]);
#pragma unroll
        for (int j = 0; j < 64; j++) h[j] = selu(h[j]);

        // ----- layer 2: 64 -> 64 -----
        ull acc2[32];
        const ull* b2p = reinterpret_cast<const ull*>(s_b2);
#pragma unroll
        for (int jj = 0; jj < 32; jj++) acc2[jj] = b2p[jj];
#pragma unroll
        for (int k = 0; k < 64; k++) {
            ull xp = pack2(h[k]);
            const ulonglong2* wr = reinterpret_cast<const ulonglong2*>(s_w2 + k * 64);
#pragma unroll
            for (int jj = 0; jj < 16; jj++) {
                ulonglong2 w = wr[jj];
                fma2(acc2[2 * jj + 0], w.x, xp);
                fma2(acc2[2 * jj + 1], w.y, xp);
            }
        }
#pragma unroll
        for (int jj = 0; jj < 32; jj++) unpack2(acc2[jj], h[2 * jj], h[2 * jj + 1]);
#pragma unroll
        for (int j = 0; j < 64; j++) h[j] = selu(h[j]);

        // ----- layer 3: 64 -> 32 -----
        ull acc3[16];
        const ull* b3p = reinterpret_cast<const ull*>(s_b3);
#pragma unroll
        for (int jj = 0; jj < 16; jj++) acc3[jj] = b3p[jj];
#pragma unroll
        for (int k = 0; k < 64; k++) {
            ull xp = pack2(h[k]);
            const ulonglong2* wr = reinterpret_cast<const ulonglong2*>(s_w3 + k * 32);
#pragma unroll
            for (int jj = 0; jj < 8; jj++) {
                ulonglong2 w = wr[jj];
                fma2(acc3[2 * jj + 0], w.x, xp);
                fma2(acc3[2 * jj + 1], w.y, xp);
            }
        }
#pragma unroll
        for (int jj = 0; jj < 16; jj++) unpack2(acc3[jj], y[2 * jj], y[2 * jj + 1]);
#pragma unroll
        for (int c = 0; c < 32; c++) y[c] = selu(y[c]);

        // write bonds_new (thread-private 128B row, fully written)
        float4* op = reinterpret_cast<float4*>(out_bonds + (size_t)e * 32);
#pragma unroll
        for (int q = 0; q < 8; q++)
            op[q] = make_float4(y[4 * q], y[4 * q + 1], y[4 * q + 2], y[4 * q + 3]);

        // scatter-add message to atom i1
        float* dst = g_b2a + (size_t)i1 * 32;
#pragma unroll
        for (int c = 0; c < 32; c++) atomicAdd(dst + c, y[c]);
        atomicAdd(g_cnt + i1, 1.0f);
    } else {
#pragma unroll
        for (int c = 0; c < 32; c++) y[c] = 0.f;
    }

    // column-sum of bonds_new for the state update: warp butterfly, then
    // per-warp slot, then 32 global atomics per block.
#pragma unroll
    for (int off = 16; off > 0; off >>= 1) {
#pragma unroll
        for (int c = 0; c < 32; c++) y[c] += __shfl_xor_sync(0xffffffffu, y[c], off);
    }
    int wid = tid >> 5;
    if ((tid & 31) == 0) {
#pragma unroll
        for (int c = 0; c < 32; c++) s_red[wid * 32 + c] = y[c];
    }
    __syncthreads();
    if (tid < 32) {
        float s = 0.f;
#pragma unroll
        for (int w = 0; w < 8; w++) s += s_red[w * 32 + tid];
        atomicAdd(&g_bsum[tid], s);
    }
}

// ---------------------------------------------------------------------------
// phi_v: one thread per atom
// smem: w1(6144) w2(4096) w3(2048) b1(64) b2(64) b3(32) state(32) red(256)
// ---------------------------------------------------------------------------
__global__ void __launch_bounds__(256)
phi_v_kernel(const float* __restrict__ atoms, const float* __restrict__ state,
             const float* __restrict__ w1, const float* __restrict__ b1,
             const float* __restrict__ w2, const float* __restrict__ b2,
             const float* __restrict__ w3, const float* __restrict__ b3,
             float* __restrict__ out_atoms, int n_atoms) {
    extern __shared__ float smem[];
    float* s_w1 = smem;             // 6144
    float* s_w2 = s_w1 + 6144;      // 4096
    float* s_w3 = s_w2 + 4096;      // 2048
    float* s_b1 = s_w3 + 2048;
    float* s_b2 = s_b1 + 64;
    float* s_b3 = s_b2 + 64;
    float* s_st = s_b3 + 32;
    float* s_red = s_st + 32;

    int tid = threadIdx.x;
    for (int i = tid; i < 6144; i += 256) s_w1[i] = w1[i];
    for (int i = tid; i < 4096; i += 256) s_w2[i] = w2[i];
    for (int i = tid; i < 2048; i += 256) s_w3[i] = w3[i];
    if (tid < 64) { s_b1[tid] = b1[tid]; s_b2[tid] = b2[tid]; }
    if (tid < 32) { s_b3[tid] = b3[tid]; s_st[tid] = state[tid]; }
    __syncthreads();

    int i = blockIdx.x * 256 + tid;
    bool active = i < n_atoms;
    float y[32];

    if (active) {
        float rc = 1.0f / g_cnt[i];

        ull acc[32];
        const ull* b1p = reinterpret_cast<const ull*>(s_b1);
#pragma unroll
        for (int jj = 0; jj < 32; jj++) acc[jj] = b1p[jj];

        const float4* bv = reinterpret_cast<const float4*>(g_b2a + (size_t)i * 32);
        const float4* av = reinterpret_cast<const float4*>(atoms + (size_t)i * 32);
        const float4* sv = reinterpret_cast<const float4*>(s_st);
#pragma unroll
        for (int kk = 0; kk < 8; kk++) {
            float4 v = bv[kk];
            v.x *= rc; v.y *= rc; v.z *= rc; v.w *= rc;
            acc64_f4(acc, v, s_w1 + (kk * 4) * 64);
        }
#pragma unroll
        for (int kk = 0; kk < 8; kk++) acc64_f4(acc, av[kk], s_w1 + (32 + kk * 4) * 64);
#pragma unroll
        for (int kk = 0; kk < 8; kk++) acc64_f4(acc, sv[kk], s_w1 + (64 + kk * 4) * 64);

        float h[64];
#pragma unroll
        for (int jj = 0; jj < 32; jj++) unpack2(acc[jj], h[2 * jj], h[2 * jj + 1]);
#pragma unroll
        for (int j = 0; j < 64; j++) h[j] = selu(h[j]);

        ull acc2[32];
        const ull* b2p = reinterpret_cast<const ull*>(s_b2);
#pragma unroll
        for (int jj = 0; jj < 32; jj++) acc2[jj] = b2p[jj];
#pragma unroll
        for (int k = 0; k < 64; k++) {
            ull xp = pack2(h[k]);
            const ulonglong2* wr = reinterpret_cast<const ulonglong2*>(s_w2 + k * 64);
#pragma unroll
            for (int jj = 0; jj < 16; jj++) {
                ulonglong2 w = wr[jj];
                fma2(acc2[2 * jj + 0], w.x, xp);
                fma2(acc2[2 * jj + 1], w.y, xp);
            }
        }
#pragma unroll
        for (int jj = 0; jj < 32; jj++) unpack2(acc2[jj], h[2 * jj], h[2 * jj + 1]);
#pragma unroll
        for (int j = 0; j < 64; j++) h[j] = selu(h[j]);

        ull acc3[16];
        const ull* b3p = reinterpret_cast<const ull*>(s_b3);
#pragma unroll
        for (int jj = 0; jj < 16; jj++) acc3[jj] = b3p[jj];
#pragma unroll
        for (int k = 0; k < 64; k++) {
            ull xp = pack2(h[k]);
            const ulonglong2* wr = reinterpret_cast<const ulonglong2*>(s_w3 + k * 32);
#pragma unroll
            for (int jj = 0; jj < 8; jj++) {
                ulonglong2 w = wr[jj];
                fma2(acc3[2 * jj + 0], w.x, xp);
                fma2(acc3[2 * jj + 1], w.y, xp);
            }
        }
#pragma unroll
        for (int jj = 0; jj < 16; jj++) unpack2(acc3[jj], y[2 * jj], y[2 * jj + 1]);
#pragma unroll
        for (int c = 0; c < 32; c++) y[c] = selu(y[c]);

        float4* op = reinterpret_cast<float4*>(out_atoms + (size_t)i * 32);
#pragma unroll
        for (int q = 0; q < 8; q++)
            op[q] = make_float4(y[4 * q], y[4 * q + 1], y[4 * q + 2], y[4 * q + 3]);
    } else {
#pragma unroll
        for (int c = 0; c < 32; c++) y[c] = 0.f;
    }

#pragma unroll
    for (int off = 16; off > 0; off >>= 1) {
#pragma unroll
        for (int c = 0; c < 32; c++) y[c] += __shfl_xor_sync(0xffffffffu, y[c], off);
    }
    int wid = tid >> 5;
    if ((tid & 31) == 0) {
#pragma unroll
        for (int c = 0; c < 32; c++) s_red[wid * 32 + c] = y[c];
    }
    __syncthreads();
    if (tid < 32) {
        float s = 0.f;
#pragma unroll
        for (int w = 0; w < 8; w++) s += s_red[w * 32 + tid];
        atomicAdd(&g_asum[tid], s);
    }
}

// ---------------------------------------------------------------------------
// phi_u: single block
// ---------------------------------------------------------------------------
__global__ void phi_u_kernel(const float* __restrict__ state,
                             const float* __restrict__ w1, const float* __restrict__ b1,
                             const float* __restrict__ w2, const float* __restrict__ b2,
                             const float* __restrict__ w3, const float* __restrict__ b3,
                             float* __restrict__ out_state,
                             float inv_nb, float inv_na) {
    __shared__ float x[96], h1[64], h2[64];
    int t = threadIdx.x;
    if (t < 32) {
        x[t] = g_bsum[t] * inv_nb;
        x[32 + t] = g_asum[t] * inv_na;
        x[64 + t] = state[t];
    }
    __syncthreads();
    if (t < 64) {
        float a = b1[t];
        for (int k = 0; k < 96; k++) a += x[k] * w1[k * 64 + t];
        h1[t] = selu(a);
    }
    __syncthreads();
    if (t < 64) {
        float a = b2[t];
        for (int k = 0; k < 64; k++) a += h1[k] * w2[k * 64 + t];
        h2[t] = selu(a);
    }
    __syncthreads();
    if (t < 32) {
        float a = b3[t];
        for (int k = 0; k < 64; k++) a += h2[k] * w3[k * 32 + t];
        out_state[t] = selu(a);
    }
}

// ---------------------------------------------------------------------------
// launch
// ---------------------------------------------------------------------------
extern "C" void kernel_launch(void* const* d_in, const int* in_sizes, int n_in,
                              void* d_out, int out_size) {
    const float* bonds = (const float*)d_in[0];
    const int* ba1 = (const int*)d_in[1];
    const int* ba2 = (const int*)d_in[2];
    const float* atoms = (const float*)d_in[3];
    const float* state = (const float*)d_in[4];
    const float* e_w1 = (const float*)d_in[5];
    const float* e_b1 = (const float*)d_in[6];
    const float* e_w2 = (const float*)d_in[7];
    const float* e_b2 = (const float*)d_in[8];
    const float* e_w3 = (const float*)d_in[9];
    const float* e_b3 = (const float*)d_in[10];
    const float* v_w1 = (const float*)d_in[11];
    const float* v_b1 = (const float*)d_in[12];
    const float* v_w2 = (const float*)d_in[13];
    const float* v_b2 = (const float*)d_in[14];
    const float* v_w3 = (const float*)d_in[15];
    const float* v_b3 = (const float*)d_in[16];
    const float* u_w1 = (const float*)d_in[17];
    const float* u_b1 = (const float*)d_in[18];
    const float* u_w2 = (const float*)d_in[19];
    const float* u_b2 = (const float*)d_in[20];
    const float* u_w3 = (const float*)d_in[21];
    const float* u_b3 = (const float*)d_in[22];

    int n_bonds = in_sizes[0] / 32;
    int n_atoms = in_sizes[3] / 32;

    float* out = (float*)d_out;
    float* out_bonds = out;
    float* out_atoms = out + (size_t)n_bonds * 32;
    float* out_state = out_atoms + (size_t)n_atoms * 32;

    const int SMEM_E = (8192 + 4096 + 2048 + 64 + 64 + 32 + 32 + 256) * 4;  // 59136
    const int SMEM_V = (6144 + 4096 + 2048 + 64 + 64 + 32 + 32 + 256) * 4;  // 50944
    cudaFuncSetAttribute(phi_e_kernel, cudaFuncAttributeMaxDynamicSharedMemorySize, SMEM_E);
    cudaFuncSetAttribute(phi_v_kernel, cudaFuncAttributeMaxDynamicSharedMemorySize, SMEM_V);

    zero_kernel<<<512, 256>>>(n_atoms);
    phi_e_kernel<<<(n_bonds + 255) / 256, 256, SMEM_E>>>(
        bonds, ba1, ba2, atoms, state,
        e_w1, e_b1, e_w2, e_b2, e_w3, e_b3, out_bonds, n_bonds);
    phi_v_kernel<<<(n_atoms + 255) / 256, 256, SMEM_V>>>(
        atoms, state, v_w1, v_b1, v_w2, v_b2, v_w3, v_b3, out_atoms, n_atoms);
    phi_u_kernel<<<1, 96>>>(state, u_w1, u_b1, u_w2, u_b2, u_w3, u_b3,
                            out_state, 1.0f / n_bonds, 1.0f / n_atoms);
}

// round 3
// speedup vs baseline: 1.4799x; 1.4799x over previous
#include <cuda_runtime.h>

// ---------------------------------------------------------------------------
// MegNet layer, round 2 (resubmit — round-2 bench was an infra failure).
//  - Factorized layer 1: proj1[i1] + proj2[i2] + bonds@Wb + c1(state,bias)
//  - Quad-split: 4 lanes per bond/atom, 16 outputs per lane, shfl input bcast
//  - Chunk-permuted smem weights for conflict-free multicast LDS.128
//  - f32x2 packed FMA throughout, fast SELU, v4 global reductions
// Output layout: [bonds_new (E*32) | atoms_new (N*32) | state_new (32)]
// ---------------------------------------------------------------------------

#define MAX_ATOMS 100000

__device__ __align__(16) float g_proj[MAX_ATOMS * 128];  // [atom][0:64)=a1-part, [64:128)=a2-part
__device__ __align__(16) float g_b2a[MAX_ATOMS * 32];
__device__ float g_cnt[MAX_ATOMS];
__device__ float g_bsum[32];
__device__ float g_asum[32];
__device__ float g_c1e[64];
__device__ float g_c1v[64];

typedef unsigned long long ull;

__device__ __forceinline__ ull pack2(float x) {
    ull r; asm("mov.b64 %0, {%1, %1};" : "=l"(r) : "f"(x)); return r;
}
__device__ __forceinline__ ull packf2(float lo, float hi) {
    ull r; asm("mov.b64 %0, {%1, %2};" : "=l"(r) : "f"(lo), "f"(hi)); return r;
}
__device__ __forceinline__ void fma2(ull& a, ull w, ull x) {
    asm("fma.rn.f32x2 %0, %1, %2, %0;" : "+l"(a) : "l"(w), "l"(x));
}
__device__ __forceinline__ void add2(ull& a, ull b) {
    asm("add.rn.f32x2 %0, %0, %1;" : "+l"(a) : "l"(b));
}
__device__ __forceinline__ float2 unpk(ull v) {
    float2 f; asm("mov.b64 {%0, %1}, %2;" : "=f"(f.x), "=f"(f.y) : "l"(v)); return f;
}

// selu: lam*x (x>0) else lam*alpha*(exp(x)-1). Fast expf path; abs error
// well inside the 1e-3 budget.
__device__ __forceinline__ float selu(float x) {
    const float L = 1.0507009873554805f;
    const float LA = 1.7580993408473766f;
    float e = __expf(x);
    float n = fmaf(LA, e, -LA);
    float p = L * x;
    return x > 0.f ? p : n;
}

// ---------------------------------------------------------------------------
// zero scratch (every replay: atomics accumulate)
// ---------------------------------------------------------------------------
__global__ void zero_kernel(int n_atoms) {
    int idx = blockIdx.x * blockDim.x + threadIdx.x;
    int stride = gridDim.x * blockDim.x;
    float4 z = make_float4(0.f, 0.f, 0.f, 0.f);
    float4* p = reinterpret_cast<float4*>(g_b2a);
    int n4 = n_atoms * 8;
    for (int i = idx; i < n4; i += stride) p[i] = z;
    for (int i = idx; i < n_atoms; i += stride) g_cnt[i] = 0.f;
    if (blockIdx.x == 0 && threadIdx.x < 32) {
        g_bsum[threadIdx.x] = 0.f; g_asum[threadIdx.x] = 0.f;
    }
}

// ---------------------------------------------------------------------------
// prep: atom projections through e_w1 rows [0:32) and [32:64), plus the
// state+bias constant vectors for phi_e and phi_v.
// Quad per atom: lane computes 16 outputs of each projection.
// ---------------------------------------------------------------------------
__global__ void __launch_bounds__(256)
prep_kernel(const float* __restrict__ atoms, const float* __restrict__ state,
            const float* __restrict__ e_w1, const float* __restrict__ e_b1,
            const float* __restrict__ v_w1, const float* __restrict__ v_b1,
            int n_atoms) {
    __shared__ float s_p1[32 * 64], s_p2[32 * 64];
    int tid = threadIdx.x;
    // chunk-permuted load: dst chunk c holds src floats (c&3)*16+(c>>2)*4+r
    for (int idx = tid; idx < 2048; idx += 256) {
        int k = idx >> 6, p = idx & 63, c = p >> 2, r = p & 3;
        int j = (c & 3) * 16 + (c >> 2) * 4 + r;
        s_p1[idx] = e_w1[k * 64 + j];
        s_p2[idx] = e_w1[(32 + k) * 64 + j];
    }
    if (blockIdx.x == 0 && tid < 64) {
        float a = e_b1[tid], b = v_b1[tid];
        for (int k = 0; k < 32; k++) {
            float s = state[k];
            a += s * e_w1[(96 + k) * 64 + tid];
            b += s * v_w1[(64 + k) * 64 + tid];
        }
        g_c1e[tid] = a; g_c1v[tid] = b;
    }
    __syncthreads();

    int quad = tid >> 2, q = tid & 3;
    int i = blockIdx.x * 64 + quad;
    bool active = i < n_atoms;
    int ic = active ? i : 0;

    float x[8];
    {
        const float4* xp = reinterpret_cast<const float4*>(atoms + (size_t)ic * 32 + q * 8);
        float4 a = xp[0], b = xp[1];
        x[0]=a.x; x[1]=a.y; x[2]=a.z; x[3]=a.w; x[4]=b.x; x[5]=b.y; x[6]=b.z; x[7]=b.w;
    }
    ull a1[8], a2[8];
#pragma unroll
    for (int m = 0; m < 8; m++) { a1[m] = 0ull; a2[m] = 0ull; }
    for (int o = 0; o < 4; o++) {
#pragma unroll
        for (int r = 0; r < 8; r++) {
            int k = o * 8 + r;
            float xk = __shfl_sync(0xffffffffu, x[r], o, 4);
            ull xp = pack2(xk);
            const ulonglong2* w1r = reinterpret_cast<const ulonglong2*>(s_p1 + (k << 6));
            const ulonglong2* w2r = reinterpret_cast<const ulonglong2*>(s_p2 + (k << 6));
#pragma unroll
            for (int m = 0; m < 4; m++) {
                ulonglong2 wa = w1r[m * 4 + q];
                ulonglong2 wb = w2r[m * 4 + q];
                fma2(a1[2*m], wa.x, xp); fma2(a1[2*m+1], wa.y, xp);
                fma2(a2[2*m], wb.x, xp); fma2(a2[2*m+1], wb.y, xp);
            }
        }
    }
    if (active) {
        float4* d1 = reinterpret_cast<float4*>(g_proj + (size_t)i * 128 + q * 16);
        float4* d2 = reinterpret_cast<float4*>(g_proj + (size_t)i * 128 + 64 + q * 16);
#pragma unroll
        for (int m = 0; m < 4; m++) {
            float2 lo = unpk(a1[2*m]), hi = unpk(a1[2*m+1]);
            d1[m] = make_float4(lo.x, lo.y, hi.x, hi.y);
            lo = unpk(a2[2*m]); hi = unpk(a2[2*m+1]);
            d2[m] = make_float4(lo.x, lo.y, hi.x, hi.y);
        }
    }
}

// ---------------------------------------------------------------------------
// phi_e: quad per bond. 64 bonds per block.
// ---------------------------------------------------------------------------
__global__ void __launch_bounds__(256, 3)
phi_e_kernel(const float* __restrict__ bonds,
             const int* __restrict__ ba1, const int* __restrict__ ba2,
             const float* __restrict__ e_w1,
             const float* __restrict__ e_w2, const float* __restrict__ e_b2,
             const float* __restrict__ e_w3, const float* __restrict__ e_b3,
             float* __restrict__ out_bonds, int n_bonds) {
    extern __shared__ float sm[];
    float* s_wb = sm;             // 2048  (e_w1 rows 64..95, permuted)
    float* s_w2 = s_wb + 2048;    // 4096
    float* s_w3 = s_w2 + 4096;    // 2048
    float* s_b2 = s_w3 + 2048;    // 64
    float* s_b3 = s_b2 + 64;      // 32
    float* s_c1 = s_b3 + 32;      // 64
    float* s_red = s_c1 + 64;     // 256

    int tid = threadIdx.x;
    const float* wb = e_w1 + 64 * 64;
    for (int idx = tid; idx < 2048; idx += 256) {
        int k = idx >> 6, p = idx & 63, c = p >> 2, r = p & 3;
        s_wb[idx] = wb[k * 64 + (c & 3) * 16 + (c >> 2) * 4 + r];
    }
    for (int idx = tid; idx < 4096; idx += 256) {
        int k = idx >> 6, p = idx & 63, c = p >> 2, r = p & 3;
        s_w2[idx] = e_w2[k * 64 + (c & 3) * 16 + (c >> 2) * 4 + r];
    }
    for (int idx = tid; idx < 2048; idx += 256) {
        int k = idx >> 5, p = idx & 31, c = p >> 2, r = p & 3;
        s_w3[idx] = e_w3[k * 32 + (c & 3) * 8 + (c >> 2) * 4 + r];
    }
    if (tid < 64) { s_b2[tid] = e_b2[tid]; s_c1[tid] = g_c1e[tid]; }
    if (tid < 32) s_b3[tid] = e_b3[tid];
    __syncthreads();

    int quad = tid >> 2, q = tid & 3;
    int e = blockIdx.x * 64 + quad;
    bool active = e < n_bonds;
    int ec = active ? e : 0;
    int i1 = ba1[ec], i2 = ba2[ec];

    float x[8];
    {
        const float4* xp = reinterpret_cast<const float4*>(bonds + (size_t)ec * 32 + q * 8);
        float4 a = xp[0], b = xp[1];
        x[0]=a.x; x[1]=a.y; x[2]=a.z; x[3]=a.w; x[4]=b.x; x[5]=b.y; x[6]=b.z; x[7]=b.w;
    }

    // init: c1 + proj1[i1] + proj2[i2]
    ull acc[8];
    {
        const ulonglong2* c1p = reinterpret_cast<const ulonglong2*>(s_c1);
        const float4* p1 = reinterpret_cast<const float4*>(g_proj + (size_t)i1 * 128 + q * 16);
        const float4* p2 = reinterpret_cast<const float4*>(g_proj + (size_t)i2 * 128 + 64 + q * 16);
#pragma unroll
        for (int m = 0; m < 4; m++) {
            ulonglong2 cc = c1p[q * 4 + m];
            float4 a = p1[m], b = p2[m];
            ull t0 = cc.x, t1 = cc.y;
            add2(t0, packf2(a.x, a.y)); add2(t1, packf2(a.z, a.w));
            add2(t0, packf2(b.x, b.y)); add2(t1, packf2(b.z, b.w));
            acc[2*m] = t0; acc[2*m+1] = t1;
        }
    }

    // layer 1 bond part: k = 0..31
    for (int o = 0; o < 4; o++) {
#pragma unroll
        for (int r = 0; r < 8; r++) {
            float xk = __shfl_sync(0xffffffffu, x[r], o, 4);
            ull xp = pack2(xk);
            const ulonglong2* wr = reinterpret_cast<const ulonglong2*>(s_wb + ((o * 8 + r) << 6));
#pragma unroll
            for (int m = 0; m < 4; m++) {
                ulonglong2 w = wr[m * 4 + q];
                fma2(acc[2*m], w.x, xp); fma2(acc[2*m+1], w.y, xp);
            }
        }
    }
    float h1[16];
#pragma unroll
    for (int m = 0; m < 4; m++) {
        float2 a = unpk(acc[2*m]), b = unpk(acc[2*m+1]);
        h1[4*m] = selu(a.x); h1[4*m+1] = selu(a.y);
        h1[4*m+2] = selu(b.x); h1[4*m+3] = selu(b.y);
    }

    // layer 2: 64 -> 64
    ull acc2[8];
    {
        const ulonglong2* bp = reinterpret_cast<const ulonglong2*>(s_b2);
#pragma unroll
        for (int m = 0; m < 4; m++) { ulonglong2 bb = bp[q * 4 + m]; acc2[2*m] = bb.x; acc2[2*m+1] = bb.y; }
    }
    for (int o = 0; o < 4; o++) {
#pragma unroll
        for (int r = 0; r < 16; r++) {
            float xk = __shfl_sync(0xffffffffu, h1[r], o, 4);
            ull xp = pack2(xk);
            const ulonglong2* wr = reinterpret_cast<const ulonglong2*>(s_w2 + ((o * 16 + r) << 6));
#pragma unroll
            for (int m = 0; m < 4; m++) {
                ulonglong2 w = wr[m * 4 + q];
                fma2(acc2[2*m], w.x, xp); fma2(acc2[2*m+1], w.y, xp);
            }
        }
    }
    float h2[16];
#pragma unroll
    for (int m = 0; m < 4; m++) {
        float2 a = unpk(acc2[2*m]), b = unpk(acc2[2*m+1]);
        h2[4*m] = selu(a.x); h2[4*m+1] = selu(a.y);
        h2[4*m+2] = selu(b.x); h2[4*m+3] = selu(b.y);
    }

    // layer 3: 64 -> 32
    ull acc3[4];
    {
        const ulonglong2* bp = reinterpret_cast<const ulonglong2*>(s_b3);
#pragma unroll
        for (int m = 0; m < 2; m++) { ulonglong2 bb = bp[q * 2 + m]; acc3[2*m] = bb.x; acc3[2*m+1] = bb.y; }
    }
    for (int o = 0; o < 4; o++) {
#pragma unroll
        for (int r = 0; r < 16; r++) {
            float xk = __shfl_sync(0xffffffffu, h2[r], o, 4);
            ull xp = pack2(xk);
            const ulonglong2* wr = reinterpret_cast<const ulonglong2*>(s_w3 + ((o * 16 + r) << 5));
#pragma unroll
            for (int m = 0; m < 2; m++) {
                ulonglong2 w = wr[m * 4 + q];
                fma2(acc3[2*m], w.x, xp); fma2(acc3[2*m+1], w.y, xp);
            }
        }
    }
    float y[8];
#pragma unroll
    for (int m = 0; m < 2; m++) {
        float2 a = unpk(acc3[2*m]), b = unpk(acc3[2*m+1]);
        y[4*m] = selu(a.x); y[4*m+1] = selu(a.y);
        y[4*m+2] = selu(b.x); y[4*m+3] = selu(b.y);
    }

    if (active) {
        float4* op = reinterpret_cast<float4*>(out_bonds + (size_t)e * 32 + q * 8);
        op[0] = make_float4(y[0], y[1], y[2], y[3]);
        op[1] = make_float4(y[4], y[5], y[6], y[7]);
        float* dst = g_b2a + (size_t)i1 * 32 + q * 8;
        asm volatile("red.global.add.v4.f32 [%0], {%1,%2,%3,%4};"
                     :: "l"(dst), "f"(y[0]), "f"(y[1]), "f"(y[2]), "f"(y[3]) : "memory");
        asm volatile("red.global.add.v4.f32 [%0], {%1,%2,%3,%4};"
                     :: "l"(dst + 4), "f"(y[4]), "f"(y[5]), "f"(y[6]), "f"(y[7]) : "memory");
        if (q == 0) atomicAdd(g_cnt + i1, 1.0f);
    } else {
#pragma unroll
        for (int j = 0; j < 8; j++) y[j] = 0.f;
    }

    // column sums of bonds_new
#pragma unroll
    for (int off = 4; off <= 16; off <<= 1) {
#pragma unroll
        for (int j = 0; j < 8; j++) y[j] += __shfl_xor_sync(0xffffffffu, y[j], off);
    }
    int lane = tid & 31, wid = tid >> 5;
    if (lane < 4) {
#pragma unroll
        for (int j = 0; j < 8; j++) s_red[wid * 32 + lane * 8 + j] = y[j];
    }
    __syncthreads();
    if (tid < 32) {
        float s = 0.f;
#pragma unroll
        for (int w = 0; w < 8; w++) s += s_red[w * 32 + tid];
        atomicAdd(&g_bsum[tid], s);
    }
}

// ---------------------------------------------------------------------------
// phi_v: quad per atom. Input: [b2a/cnt (32) | atoms (32)]; state folded in c1v.
// ---------------------------------------------------------------------------
__global__ void __launch_bounds__(256, 3)
phi_v_kernel(const float* __restrict__ atoms,
             const float* __restrict__ v_w1,
             const float* __restrict__ v_w2, const float* __restrict__ v_b2,
             const float* __restrict__ v_w3, const float* __restrict__ v_b3,
             float* __restrict__ out_atoms, int n_atoms) {
    extern __shared__ float sm[];
    float* s_w1 = sm;             // 4096 (v_w1 rows 0..63, permuted)
    float* s_w2 = s_w1 + 4096;    // 4096
    float* s_w3 = s_w2 + 4096;    // 2048
    float* s_b2 = s_w3 + 2048;    // 64
    float* s_b3 = s_b2 + 64;      // 32
    float* s_c1 = s_b3 + 32;      // 64
    float* s_red = s_c1 + 64;     // 256

    int tid = threadIdx.x;
    for (int idx = tid; idx < 4096; idx += 256) {
        int k = idx >> 6, p = idx & 63, c = p >> 2, r = p & 3;
        int j = (c & 3) * 16 + (c >> 2) * 4 + r;
        s_w1[idx] = v_w1[k * 64 + j];
        s_w2[idx] = v_w2[k * 64 + j];
    }
    for (int idx = tid; idx < 2048; idx += 256) {
        int k = idx >> 5, p = idx & 31, c = p >> 2, r = p & 3;
        s_w3[idx] = v_w3[k * 32 + (c & 3) * 8 + (c >> 2) * 4 + r];
    }
    if (tid < 64) { s_b2[tid] = v_b2[tid]; s_c1[tid] = g_c1v[tid]; }
    if (tid < 32) s_b3[tid] = v_b3[tid];
    __syncthreads();

    int quad = tid >> 2, q = tid & 3;
    int i = blockIdx.x * 64 + quad;
    bool active = i < n_atoms;
    int ic = active ? i : 0;

    float rc = 1.0f / g_cnt[ic];
    float x[16];
    {
        const float4* src = (q < 2)
            ? reinterpret_cast<const float4*>(g_b2a + (size_t)ic * 32 + q * 16)
            : reinterpret_cast<const float4*>(atoms + (size_t)ic * 32 + (q - 2) * 16);
        float sc = (q < 2) ? rc : 1.0f;
#pragma unroll
        for (int m = 0; m < 4; m++) {
            float4 v = src[m];
            x[4*m] = v.x * sc; x[4*m+1] = v.y * sc; x[4*m+2] = v.z * sc; x[4*m+3] = v.w * sc;
        }
    }

    // layer 1: 64 -> 64, bias = c1v
    ull acc[8];
    {
        const ulonglong2* cp = reinterpret_cast<const ulonglong2*>(s_c1);
#pragma unroll
        for (int m = 0; m < 4; m++) { ulonglong2 bb = cp[q * 4 + m]; acc[2*m] = bb.x; acc[2*m+1] = bb.y; }
    }
    for (int o = 0; o < 4; o++) {
#pragma unroll
        for (int r = 0; r < 16; r++) {
            float xk = __shfl_sync(0xffffffffu, x[r], o, 4);
            ull xp = pack2(xk);
            const ulonglong2* wr = reinterpret_cast<const ulonglong2*>(s_w1 + ((o * 16 + r) << 6));
#pragma unroll
            for (int m = 0; m < 4; m++) {
                ulonglong2 w = wr[m * 4 + q];
                fma2(acc[2*m], w.x, xp); fma2(acc[2*m+1], w.y, xp);
            }
        }
    }
    float h1[16];
#pragma unroll
    for (int m = 0; m < 4; m++) {
        float2 a = unpk(acc[2*m]), b = unpk(acc[2*m+1]);
        h1[4*m] = selu(a.x); h1[4*m+1] = selu(a.y);
        h1[4*m+2] = selu(b.x); h1[4*m+3] = selu(b.y);
    }

    // layer 2
    ull acc2[8];
    {
        const ulonglong2* bp = reinterpret_cast<const ulonglong2*>(s_b2);
#pragma unroll
        for (int m = 0; m < 4; m++) { ulonglong2 bb = bp[q * 4 + m]; acc2[2*m] = bb.x; acc2[2*m+1] = bb.y; }
    }
    for (int o = 0; o < 4; o++) {
#pragma unroll
        for (int r = 0; r < 16; r++) {
            float xk = __shfl_sync(0xffffffffu, h1[r], o, 4);
            ull xp = pack2(xk);
            const ulonglong2* wr = reinterpret_cast<const ulonglong2*>(s_w2 + ((o * 16 + r) << 6));
#pragma unroll
            for (int m = 0; m < 4; m++) {
                ulonglong2 w = wr[m * 4 + q];
                fma2(acc2[2*m], w.x, xp); fma2(acc2[2*m+1], w.y, xp);
            }
        }
    }
    float h2[16];
#pragma unroll
    for (int m = 0; m < 4; m++) {
        float2 a = unpk(acc2[2*m]), b = unpk(acc2[2*m+1]);
        h2[4*m] = selu(a.x); h2[4*m+1] = selu(a.y);
        h2[4*m+2] = selu(b.x); h2[4*m+3] = selu(b.y);
    }

    // layer 3
    ull acc3[4];
    {
        const ulonglong2* bp = reinterpret_cast<const ulonglong2*>(s_b3);
#pragma unroll
        for (int m = 0; m < 2; m++) { ulonglong2 bb = bp[q * 2 + m]; acc3[2*m] = bb.x; acc3[2*m+1] = bb.y; }
    }
    for (int o = 0; o < 4; o++) {
#pragma unroll
        for (int r = 0; r < 16; r++) {
            float xk = __shfl_sync(0xffffffffu, h2[r], o, 4);
            ull xp = pack2(xk);
            const ulonglong2* wr = reinterpret_cast<const ulonglong2*>(s_w3 + ((o * 16 + r) << 5));
#pragma unroll
            for (int m = 0; m < 2; m++) {
                ulonglong2 w = wr[m * 4 + q];
                fma2(acc3[2*m], w.x, xp); fma2(acc3[2*m+1], w.y, xp);
            }
        }
    }
    float y[8];
#pragma unroll
    for (int m = 0; m < 2; m++) {
        float2 a = unpk(acc3[2*m]), b = unpk(acc3[2*m+1]);
        y[4*m] = selu(a.x); y[4*m+1] = selu(a.y);
        y[4*m+2] = selu(b.x); y[4*m+3] = selu(b.y);
    }

    if (active) {
        float4* op = reinterpret_cast<float4*>(out_atoms + (size_t)i * 32 + q * 8);
        op[0] = make_float4(y[0], y[1], y[2], y[3]);
        op[1] = make_float4(y[4], y[5], y[6], y[7]);
    } else {
#pragma unroll
        for (int j = 0; j < 8; j++) y[j] = 0.f;
    }

#pragma unroll
    for (int off = 4; off <= 16; off <<= 1) {
#pragma unroll
        for (int j = 0; j < 8; j++) y[j] += __shfl_xor_sync(0xffffffffu, y[j], off);
    }
    int lane = tid & 31, wid = tid >> 5;
    if (lane < 4) {
#pragma unroll
        for (int j = 0; j < 8; j++) s_red[wid * 32 + lane * 8 + j] = y[j];
    }
    __syncthreads();
    if (tid < 32) {
        float s = 0.f;
#pragma unroll
        for (int w = 0; w < 8; w++) s += s_red[w * 32 + tid];
        atomicAdd(&g_asum[tid], s);
    }
}

// ---------------------------------------------------------------------------
// phi_u: single block
// ---------------------------------------------------------------------------
__global__ void phi_u_kernel(const float* __restrict__ state,
                             const float* __restrict__ w1, const float* __restrict__ b1,
                             const float* __restrict__ w2, const float* __restrict__ b2,
                             const float* __restrict__ w3, const float* __restrict__ b3,
                             float* __restrict__ out_state,
                             float inv_nb, float inv_na) {
    __shared__ float x[96], h1[64], h2[64];
    int t = threadIdx.x;
    if (t < 32) {
        x[t] = g_bsum[t] * inv_nb;
        x[32 + t] = g_asum[t] * inv_na;
        x[64 + t] = state[t];
    }
    __syncthreads();
    if (t < 64) {
        float a = b1[t];
        for (int k = 0; k < 96; k++) a += x[k] * w1[k * 64 + t];
        h1[t] = selu(a);
    }
    __syncthreads();
    if (t < 64) {
        float a = b2[t];
        for (int k = 0; k < 64; k++) a += h1[k] * w2[k * 64 + t];
        h2[t] = selu(a);
    }
    __syncthreads();
    if (t < 32) {
        float a = b3[t];
        for (int k = 0; k < 64; k++) a += h2[k] * w3[k * 32 + t];
        out_state[t] = selu(a);
    }
}

// ---------------------------------------------------------------------------
// launch
// ---------------------------------------------------------------------------
extern "C" void kernel_launch(void* const* d_in, const int* in_sizes, int n_in,
                              void* d_out, int out_size) {
    const float* bonds = (const float*)d_in[0];
    const int* ba1 = (const int*)d_in[1];
    const int* ba2 = (const int*)d_in[2];
    const float* atoms = (const float*)d_in[3];
    const float* state = (const float*)d_in[4];
    const float* e_w1 = (const float*)d_in[5];
    const float* e_b1 = (const float*)d_in[6];
    const float* e_w2 = (const float*)d_in[7];
    const float* e_b2 = (const float*)d_in[8];
    const float* e_w3 = (const float*)d_in[9];
    const float* e_b3 = (const float*)d_in[10];
    const float* v_w1 = (const float*)d_in[11];
    const float* v_b1 = (const float*)d_in[12];
    const float* v_w2 = (const float*)d_in[13];
    const float* v_b2 = (const float*)d_in[14];
    const float* v_w3 = (const float*)d_in[15];
    const float* v_b3 = (const float*)d_in[16];
    const float* u_w1 = (const float*)d_in[17];
    const float* u_b1 = (const float*)d_in[18];
    const float* u_w2 = (const float*)d_in[19];
    const float* u_b2 = (const float*)d_in[20];
    const float* u_w3 = (const float*)d_in[21];
    const float* u_b3 = (const float*)d_in[22];

    int n_bonds = in_sizes[0] / 32;
    int n_atoms = in_sizes[3] / 32;

    float* out = (float*)d_out;
    float* out_bonds = out;
    float* out_atoms = out + (size_t)n_bonds * 32;
    float* out_state = out_atoms + (size_t)n_atoms * 32;

    const int SMEM_E = (2048 + 4096 + 2048 + 64 + 32 + 64 + 256) * 4;  // 34432
    const int SMEM_V = (4096 + 4096 + 2048 + 64 + 32 + 64 + 256) * 4;  // 42624

    int grid_e = (n_bonds + 63) / 64;
    int grid_a = (n_atoms + 63) / 64;

    zero_kernel<<<1024, 256>>>(n_atoms);
    prep_kernel<<<grid_a, 256>>>(atoms, state, e_w1, e_b1, v_w1, v_b1, n_atoms);
    phi_e_kernel<<<grid_e, 256, SMEM_E>>>(
        bonds, ba1, ba2, e_w1, e_w2, e_b2, e_w3, e_b3, out_bonds, n_bonds);
    phi_v_kernel<<<grid_a, 256, SMEM_V>>>(
        atoms, v_w1, v_w2, v_b2, v_w3, v_b3, out_atoms, n_atoms);
    phi_u_kernel<<<1, 96>>>(state, u_w1, u_b1, u_w2, u_b2, u_w3, u_b3,
                            out_state, 1.0f / n_bonds, 1.0f / n_atoms);
}